// round 11
// baseline (speedup 1.0000x reference)
#include <cuda_runtime.h>
#include <cuda_fp16.h>
#include <cstdint>

// Problem constants
#define Bn 256
#define Nn 1152        // 32*6*6 input capsules
#define On 10
#define En 16
#define OE 160         // On*En
#define Dn 8
#define NC 32          // n per k_uhat block
#define K1T (Nn / NC)  // 36 n-tiles in k_uhat
#define BC 16          // b per k_uhat block (halved: 576 blocks, 16 KB smem)
#define NTILE 128
#define NTILES 9       // 1152 / 128

// Scratch (device globals)
__device__ __half g_uhat[(size_t)Bn * Nn * OE];  // ~94 MB fp16
__device__ float  g_part[K1T * Bn * OE];         // per-tile partial s (5.9 MB)
__device__ float  g_v[Bn * OE];                  // v0, then v0+v1 (the logit vector)

// ---------------------------------------------------------------------------
// squash over E=16 within a warp-half. Requires fully-active warps.
__device__ __forceinline__ float squash_val(float sv) {
    float sq = sv * sv;
    sq += __shfl_xor_sync(0xffffffffu, sq, 1);
    sq += __shfl_xor_sync(0xffffffffu, sq, 2);
    sq += __shfl_xor_sync(0xffffffffu, sq, 4);
    sq += __shfl_xor_sync(0xffffffffu, sq, 8);
    return sv * sq / (1.0f + sq) / (sqrtf(sq) + 1e-6f);
}

// ---------------------------------------------------------------------------
// K1: u_hat[b,n,o,e] = sum_d x[b,n,d] * W[n,o,d,e]  (fp16 out)
//     + fused partial s0: g_part[tile][b][oe] = sum_{n in tile} u
// grid (36 n-tiles, 16 b-tiles) = 576 blocks, 320 thr = 4 b-groups x 80 (o,e2).
__global__ __launch_bounds__(320) void k_uhat(const float* __restrict__ x,
                                              const float* __restrict__ W) {
    int nb = blockIdx.x * NC;
    int b0 = blockIdx.y * BC;
    int t  = threadIdx.x;              // 0..319

    __shared__ float xs[BC][NC][Dn];   // 16 KB, [b][n][d]
    for (int i = t; i < BC * NC * Dn / 4; i += 320) {  // 1024 float4
        int b = i >> 6, q = i & 63;    // 64 float4 per b
        float4 v = *(const float4*)(x + ((size_t)(b0 + b) * Nn + nb) * Dn + q * 4);
        int n = q >> 1, h = q & 1;
        *(float4*)(&xs[b][n][h * 4]) = v;
    }
    __syncthreads();

    int g = t / 80, p = t - g * 80;    // g: b-group (4 b each), p: (o, e-pair)
    int o = p >> 3, e2 = p & 7;        // oe = 2*p

    float2 acc[4];
#pragma unroll
    for (int b = 0; b < 4; b++) acc[b] = make_float2(0.f, 0.f);

    __half2* uh = (__half2*)g_uhat;
    for (int n = 0; n < NC; n++) {
        float2 w[8];
        const float2* wp = (const float2*)(W + (size_t)((nb + n) * On + o) * (Dn * En)) + e2;
#pragma unroll
        for (int d = 0; d < 8; d++) w[d] = wp[d * 8];  // stride En floats = 8 float2
#pragma unroll
        for (int b = 0; b < 4; b++) {
            int bb = g * 4 + b;
            float u0 = 0.f, u1 = 0.f;
#pragma unroll
            for (int d = 0; d < 8; d++) {
                float xv = xs[bb][n][d];
                u0 = fmaf(w[d].x, xv, u0);
                u1 = fmaf(w[d].y, xv, u1);
            }
            acc[b].x += u0; acc[b].y += u1;
            uh[((size_t)(b0 + bb) * Nn + nb + n) * 80 + p] = __floats2half2_rn(u0, u1);
        }
    }
#pragma unroll
    for (int b = 0; b < 4; b++) {
        int bb = g * 4 + b;
        *(float2*)(g_part + ((size_t)blockIdx.x * Bn + b0 + bb) * OE + 2 * p) = acc[b];
    }
}

// ---------------------------------------------------------------------------
// Route iteration: logits = u . g_v ; softmax over o ; weighted partial sums.
// g_v holds v0 (iter 1) or v0+v1 (iter 2) — logits are additive from b=0.
// grid (9 tiles, 256 b), 320 threads, ~54 KB dynamic smem.
// ITER=2 traverses (tile,b) reversed to harvest the L2-resident tail of u_hat.
template <int ITER>
__global__ void k_route() {
    extern __shared__ char sm[];
    __half2* u_s = (__half2*)sm;                    // 40960 B (128 x 80 half2)
    float* v_s = (float*)(sm + NTILE * OE * 2);     // 640
    float* b1s = v_s + OE;                          // 5120
    float* cs  = b1s + NTILE * On;                  // 5120
    float* sp  = cs + NTILE * On;                   // 2560 (4 x 160)

    int tile = (ITER == 2) ? (NTILES - 1 - (int)blockIdx.x) : (int)blockIdx.x;
    int b    = (ITER == 2) ? (Bn - 1 - (int)blockIdx.y)     : (int)blockIdx.y;
    int t = threadIdx.x;
    int n0 = tile * NTILE;

    // Phase A: load fp16 u tile (40 KB) + v
    const float4* src = (const float4*)(g_uhat + ((size_t)b * Nn + n0) * OE);
    float4* dst = (float4*)u_s;
#pragma unroll
    for (int i = 0; i < 8; i++) dst[t + i * 320] = src[t + i * 320];
    if (t < OE) v_s[t] = g_v[b * OE + t];
    __syncthreads();

    // Phase B: logits b1[n,o] = dot_e(u, v), vectorized LDS.64
#pragma unroll
    for (int i = 0; i < 4; i++) {
        int pp = t + i * 320;          // 0..1279
        int n = pp / On, o = pp - n * On;
        const uint2* ur = (const uint2*)(u_s + n * 80 + o * 8);   // 4 x uint2
        const float2* vf = (const float2*)v_s + o * 8;            // 8 x float2
        float bb = 0.f;
#pragma unroll
        for (int k = 0; k < 4; k++) {
            uint2 uu = ur[k];
            float2 a0 = __half22float2(*(const __half2*)&uu.x);
            float2 a1 = __half22float2(*(const __half2*)&uu.y);
            float2 w0 = vf[2 * k], w1 = vf[2 * k + 1];
            bb = fmaf(a0.x, w0.x, bb);
            bb = fmaf(a0.y, w0.y, bb);
            bb = fmaf(a1.x, w1.x, bb);
            bb = fmaf(a1.y, w1.y, bb);
        }
        b1s[pp] = bb;
    }
    __syncthreads();

    // Phase C: softmax over o, one thread per n
    if (t < NTILE) {
        const float* br = b1s + t * On;
        float m = br[0];
#pragma unroll
        for (int o = 1; o < On; o++) m = fmaxf(m, br[o]);
        float ex[On]; float ssum = 0.f;
#pragma unroll
        for (int o = 0; o < On; o++) { ex[o] = __expf(br[o] - m); ssum += ex[o]; }
        float inv = 1.0f / ssum;
        float* cr = cs + t * On;
#pragma unroll
        for (int o = 0; o < On; o++) cr[o] = ex[o] * inv;
    }
    __syncthreads();

    // Phase D: weighted partial sums (4 n-groups x 80 oe-pairs)
    {
        int g = t / 80, p = t - g * 80;
        int o = p >> 3;
        float2 a = make_float2(0.f, 0.f);
        int nb2 = g * 32;
#pragma unroll 8
        for (int n = nb2; n < nb2 + 32; n++) {
            float c = cs[n * On + o];
            float2 uf = __half22float2(u_s[n * 80 + p]);
            a.x = fmaf(c, uf.x, a.x);
            a.y = fmaf(c, uf.y, a.y);
        }
        *(float2*)(sp + g * OE + 2 * p) = a;
    }
    __syncthreads();
    if (t < OE)
        g_part[((size_t)tile * Bn + b) * OE + t] =
            ((sp[t] + sp[OE + t]) + sp[2 * OE + t]) + sp[3 * OE + t];
}

// ---------------------------------------------------------------------------
// Reduce partials -> s -> squash. Tile axis parallelized across thread groups.
// MODE 0: s0 = 0.1*sum(36 tiles) -> v0 -> g_v   (640 thr = 4 x 160)
// MODE 1: v1 = squash(sum 9); g_v += v1         (480 thr = 3 x 160)
// MODE 2: v2 -> out                             (480 thr)
template <int MODE>
__global__ void k_finish(float* __restrict__ out) {
    constexpr int NT  = (MODE == 0) ? K1T : NTILES;  // 36 / 9
    constexpr int G   = (MODE == 0) ? 4 : 3;
    constexpr int PER = NT / G;                      // 9 / 3
    __shared__ float red[G][OE];

    int b = blockIdx.x, t = threadIdx.x;             // G*160
    int g = t / OE, oe = t - g * OE;
    float acc = 0.f;
#pragma unroll
    for (int i = 0; i < PER; i++)
        acc += g_part[((size_t)(g * PER + i) * Bn + b) * OE + oe];
    red[g][oe] = acc;
    __syncthreads();

    if (t < OE) {
        float s = red[0][t];
#pragma unroll
        for (int gg = 1; gg < G; gg++) s += red[gg][t];
        if (MODE == 0)      g_v[b * OE + t]  = squash_val(s * 0.1f);
        else if (MODE == 1) g_v[b * OE + t] += squash_val(s);
        else                out[b * OE + t]  = squash_val(s);
    }
}

// ---------------------------------------------------------------------------
extern "C" void kernel_launch(void* const* d_in, const int* in_sizes, int n_in,
                              void* d_out, int out_size) {
    const float* x = (const float*)d_in[0];
    const float* W = (const float*)d_in[1];
    if (n_in >= 2 && in_sizes[0] == 1474560) {  // defensive: swapped order
        x = (const float*)d_in[1];
        W = (const float*)d_in[0];
    }
    float* out = (float*)d_out;

    const int smem_route = NTILE * OE * 2 + (OE + 2 * NTILE * On + 4 * OE) * 4;  // ~54 KB
    cudaFuncSetAttribute(k_route<1>, cudaFuncAttributeMaxDynamicSharedMemorySize, smem_route);
    cudaFuncSetAttribute(k_route<2>, cudaFuncAttributeMaxDynamicSharedMemorySize, smem_route);

    k_uhat<<<dim3(K1T, Bn / BC), 320>>>(x, W);            // u_hat fp16 + s0 partials (576 blocks)
    k_finish<0><<<Bn, 4 * OE>>>(nullptr);                 // v0
    k_route<1><<<dim3(NTILES, Bn), 320, smem_route>>>();  // iter 1 partials
    k_finish<1><<<Bn, 3 * OE>>>(nullptr);                 // v1, g_v = v0+v1
    k_route<2><<<dim3(NTILES, Bn), 320, smem_route>>>();  // iter 2 partials (reversed)
    k_finish<2><<<Bn, 3 * OE>>>(out);                     // v2 -> d_out
}